// round 14
// baseline (speedup 1.0000x reference)
#include <cuda_runtime.h>
#include <cuda_fp16.h>
#include <cstdint>

#define INF   128
#define HIDF  256
#define OUTF  64
#define N0C   400000
#define N1C   100000
#define N2C   25000
#define E0C   1600000
#define E1C   400000

// ======================= PTX helpers =======================
__device__ __forceinline__ uint32_t smem_to_u32(const void* smem_ptr) {
    uint32_t addr;
    asm("{ .reg .u64 tmp; cvta.to.shared.u64 tmp, %1; cvt.u32.u64 %0, tmp; }"
        : "=r"(addr) : "l"(smem_ptr));
    return addr;
}
#define CP_ASYNC16(dst, src) \
    asm volatile("cp.async.cg.shared.global [%0], [%1], 16;" :: "r"(dst), "l"(src))
#define CP_COMMIT() asm volatile("cp.async.commit_group;" ::: "memory")
#define CP_WAIT(n)  asm volatile("cp.async.wait_group %0;" :: "n"(n) : "memory")
#define LDSM4(r, addr) \
    asm volatile("ldmatrix.sync.aligned.m8n8.x4.shared.b16 {%0,%1,%2,%3}, [%4];" \
        : "=r"((r)[0]), "=r"((r)[1]), "=r"((r)[2]), "=r"((r)[3]) : "r"(addr))
#define MMA16816H(d, a, b) \
    asm volatile("mma.sync.aligned.m16n8k16.row.col.f32.f16.f16.f32 " \
        "{%0,%1,%2,%3}, {%4,%5,%6,%7}, {%8,%9}, {%0,%1,%2,%3};" \
        : "+f"((d)[0]), "+f"((d)[1]), "+f"((d)[2]), "+f"((d)[3]) \
        : "r"((a)[0]), "r"((a)[1]), "r"((a)[2]), "r"((a)[3]), \
          "r"((b)[0]), "r"((b)[1]))

__device__ __forceinline__ uint32_t pack2h(float a, float b) {
    __half2 p = __floats2half2_rn(a, b);
    return *reinterpret_cast<uint32_t*>(&p);
}

// ======================= device scratch =======================
__device__ __align__(16) __half g_xc[(size_t)N0C * 256];    // [row][xn(128)|xt(128)] fp16
__device__ __align__(16) __half g_X1h[(size_t)N1C * HIDF];  // layer-1 output fp16
__device__ int g_cnt0[N1C];
__device__ int g_off0[N1C + 1];
__device__ int g_cur0[N1C];
__device__ int g_es0[E0C];
__device__ int g_cnt1[N2C];
__device__ int g_off1[N2C + 1];
__device__ int g_cur1[N2C];
__device__ int g_es1[E1C];
__device__ int g_part0[256];
__device__ int g_part1[64];
__device__ __align__(128) __half g_Bh[256 * 512];           // [N=256][K=512] combined W fp16
__device__ __align__(16) uint32_t g_W2f[64 * 512 / 2];      // W2 fp16, mma fragment order
__device__ float g_bA[HIDF];
__device__ float g_bB[HIDF];

// ======================= zero + x->fp16 convert =======================
#define ZB  489
#define CVB ((N0C * 256) / 2048)
__global__ void zero_cvt_kernel(const float* __restrict__ xn,
                                const float* __restrict__ xt) {
    int b = blockIdx.x, t = threadIdx.x;
    if (b < ZB) {
        int i = b * 256 + t;
        if (i < N1C) g_cnt0[i] = 0;
        else if (i < N1C + N2C) g_cnt1[i - N1C] = 0;
    } else {
        int cb = b - ZB;
        int idx = cb * 2048 + t * 8;
        int row = idx >> 8;
        int pos = idx & 255;
        const float* src = (pos < 128) ? (xn + (size_t)row * 128 + pos)
                                       : (xt + (size_t)row * 128 + (pos - 128));
        float4 a = __ldg(reinterpret_cast<const float4*>(src));
        float4 c = __ldg(reinterpret_cast<const float4*>(src) + 1);
        uint4 o;
        o.x = pack2h(a.x, a.y);
        o.y = pack2h(a.z, a.w);
        o.z = pack2h(c.x, c.y);
        o.w = pack2h(c.z, c.w);
        *reinterpret_cast<uint4*>(g_xc + (size_t)row * 256 + pos) = o;
    }
}

// ======================= count (atomics) + weight prep (FFMA) overlap ================
#define WCB 512
#define W2B 128
__global__ void countprep_kernel(
    const int* __restrict__ d0, const int* __restrict__ d1, int e0, int e1, int ncb,
    const float* __restrict__ Wl0, const float* __restrict__ Wr0,
    const float* __restrict__ b0,
    const float* __restrict__ Wl1, const float* __restrict__ Wr1,
    const float* __restrict__ b1,
    const float* __restrict__ Wl2, const float* __restrict__ Wr2) {
    int b = blockIdx.x, t = threadIdx.x;
    if (b < ncb) {
        int i = b * 256 + t;
        if (i < e0) atomicAdd(&g_cnt0[d0[i]], 1);
        else if (i - e0 < e1) atomicAdd(&g_cnt1[d1[i - e0]], 1);
    } else if (b < ncb + WCB) {
        int idx = (b - ncb) * 256 + t;
        int i = idx >> 8;
        int j = idx & 255;
        int blk = i >> 7;
        int il = i & 127;
        const float* M1 = (blk == 0 || blk == 2) ? Wl0 : Wr0;
        const float* M2 = (blk < 2) ? Wl1 : Wr1;
        float s = 0.f;
        #pragma unroll 8
        for (int k = 0; k < 256; k++) s = fmaf(M1[il * 256 + k], M2[k * 256 + j], s);
        g_Bh[j * 512 + i] = __float2half_rn(s);
    } else if (b < ncb + WCB + W2B) {
        int e = (b - ncb - WCB) * 256 + t;
        int n = e & 63, k = e >> 6;
        float s = (k < 256) ? Wl2[k * 64 + n] : Wr2[(k - 256) * 64 + n];
        int k16 = k >> 4, nt = n >> 3, gid = n & 7;
        int kk = k & 15, reg = kk >> 3, tig = (kk & 7) >> 1, half = kk & 1;
        int u = ((k16 * 8 + nt) * 32 + gid * 4 + tig) * 2 + reg;
        reinterpret_cast<__half*>(g_W2f)[u * 2 + half] = __float2half_rn(s);
    } else {
        int j = t;
        float sa = 0.f, sb = 0.f;
        for (int k = 0; k < 256; k++) {
            sa = fmaf(b0[k], Wl1[k * 256 + j], sa);
            sb = fmaf(b0[k], Wr1[k * 256 + j], sb);
        }
        g_bA[j] = sa;
        g_bB[j] = sb + b1[j];
    }
}

__global__ void scatterAll_kernel(const int* __restrict__ s0, const int* __restrict__ d0,
                                  const int* __restrict__ s1, const int* __restrict__ d1,
                                  int e0, int e1) {
    int i = blockIdx.x * blockDim.x + threadIdx.x;
    if (i < e0) {
        int p = atomicAdd(&g_cur0[d0[i]], 1);
        g_es0[p] = s0[i];
    } else if (i - e0 < e1) {
        int j = i - e0;
        int p = atomicAdd(&g_cur1[d1[j]], 1);
        g_es1[p] = s1[j];
    }
}

#define NB0 ((N1C + 511) / 512)
#define NB1 ((N2C + 511) / 512)

__device__ __forceinline__ void scan_part_impl(const int* __restrict__ cnt,
                                               int* __restrict__ part, int n, int bb) {
    __shared__ int ws[8];
    int base = bb * 512;
    int t = threadIdx.x;
    int i0 = base + t * 2;
    int s = 0;
    if (i0 < n) s += cnt[i0];
    if (i0 + 1 < n) s += cnt[i0 + 1];
    #pragma unroll
    for (int o = 16; o > 0; o >>= 1) s += __shfl_down_sync(0xffffffffu, s, o);
    if ((t & 31) == 0) ws[t >> 5] = s;
    __syncthreads();
    if (t == 0) {
        int tot = 0;
        #pragma unroll
        for (int i = 0; i < 8; i++) tot += ws[i];
        part[bb] = tot;
    }
}
__device__ __forceinline__ void scan_top_impl(int* __restrict__ part, int nb) {
    __shared__ int ws[8];
    int t = threadIdx.x;
    int v = (t < nb) ? part[t] : 0;
    int lane = t & 31, w = t >> 5;
    int incl = v;
    #pragma unroll
    for (int o = 1; o < 32; o <<= 1) {
        int x = __shfl_up_sync(0xffffffffu, incl, o);
        if (lane >= o) incl += x;
    }
    if (lane == 31) ws[w] = incl;
    __syncthreads();
    if (t == 0) {
        int run = 0;
        #pragma unroll
        for (int i = 0; i < 8; i++) { int tm = ws[i]; ws[i] = run; run += tm; }
    }
    __syncthreads();
    if (t < nb) part[t] = incl - v + ws[w];
    __syncthreads();
}
__device__ __forceinline__ void scan_final_impl(const int* __restrict__ cnt,
                                                const int* __restrict__ part,
                                                int* __restrict__ off,
                                                int* __restrict__ cur, int n, int bb) {
    __shared__ int ws[8];
    int base = bb * 512;
    int t = threadIdx.x;
    int i0 = base + t * 2;
    int c0 = (i0 < n) ? cnt[i0] : 0;
    int c1 = (i0 + 1 < n) ? cnt[i0 + 1] : 0;
    int s = c0 + c1;
    int lane = t & 31, w = t >> 5;
    int incl = s;
    #pragma unroll
    for (int o = 1; o < 32; o <<= 1) {
        int x = __shfl_up_sync(0xffffffffu, incl, o);
        if (lane >= o) incl += x;
    }
    if (lane == 31) ws[w] = incl;
    __syncthreads();
    if (t == 0) {
        int run = 0;
        #pragma unroll
        for (int i = 0; i < 8; i++) { int tm = ws[i]; ws[i] = run; run += tm; }
    }
    __syncthreads();
    int excl = incl - s + ws[w] + part[bb];
    if (i0 < n) { off[i0] = excl; cur[i0] = excl; }
    if (i0 + 1 < n) { off[i0 + 1] = excl + c0; cur[i0 + 1] = excl + c0; }
    if (i0 == n - 1) off[n] = excl + c0;
    else if (i0 + 1 == n - 1) off[n] = excl + c0 + c1;
}
__global__ void scanPart_all() {
    int b = blockIdx.x;
    if (b < NB0) scan_part_impl(g_cnt0, g_part0, N1C, b);
    else scan_part_impl(g_cnt1, g_part1, N2C, b - NB0);
}
__global__ void scanTop_all() {
    scan_top_impl(g_part0, NB0);
    scan_top_impl(g_part1, NB1);
}
__global__ void scanFinal_all() {
    int b = blockIdx.x;
    if (b < NB0) scan_final_impl(g_cnt0, g_part0, g_off0, g_cur0, N1C, b);
    else scan_final_impl(g_cnt1, g_part1, g_off1, g_cur1, N2C, b - NB0);
}

// ======================= shared aggregation row helper ================================
__device__ __forceinline__ void acc_u4(float* acc, uint4 v) {
    const __half2* h = reinterpret_cast<const __half2*>(&v);
    #pragma unroll
    for (int q = 0; q < 4; q++) {
        float2 f = __half22float2(h[q]);
        acc[q * 2 + 0] += f.x;
        acc[q * 2 + 1] += f.y;
    }
}

// Aggregate one dst row (512B fp16) into padded GEMM smem layout:
// chunk (lane>>2) buffer, row rl, 16B at (lane&3)*16. 8-deep edge unroll for MLP.
__device__ __forceinline__ void agg_row_smem(const int* __restrict__ off,
                                             const int* __restrict__ es,
                                             const __half* __restrict__ srcbuf,
                                             char* __restrict__ smem_agg, int d, int rl) {
    int lane = threadIdx.x & 31;
    int b = off[d], e = off[d + 1];
    const uint4* x4 = reinterpret_cast<const uint4*>(srcbuf);
    float acc[8] = {};
    int i = b;
    for (; i + 7 < e; i += 8) {
        uint4 v0 = __ldg(x4 + (size_t)es[i + 0] * 32 + lane);
        uint4 v1 = __ldg(x4 + (size_t)es[i + 1] * 32 + lane);
        uint4 v2 = __ldg(x4 + (size_t)es[i + 2] * 32 + lane);
        uint4 v3 = __ldg(x4 + (size_t)es[i + 3] * 32 + lane);
        uint4 v4 = __ldg(x4 + (size_t)es[i + 4] * 32 + lane);
        uint4 v5 = __ldg(x4 + (size_t)es[i + 5] * 32 + lane);
        uint4 v6 = __ldg(x4 + (size_t)es[i + 6] * 32 + lane);
        uint4 v7 = __ldg(x4 + (size_t)es[i + 7] * 32 + lane);
        acc_u4(acc, v0); acc_u4(acc, v1); acc_u4(acc, v2); acc_u4(acc, v3);
        acc_u4(acc, v4); acc_u4(acc, v5); acc_u4(acc, v6); acc_u4(acc, v7);
    }
    for (; i + 1 < e; i += 2) {
        uint4 v0 = __ldg(x4 + (size_t)es[i + 0] * 32 + lane);
        uint4 v1 = __ldg(x4 + (size_t)es[i + 1] * 32 + lane);
        acc_u4(acc, v0); acc_u4(acc, v1);
    }
    if (i < e) {
        uint4 v0 = __ldg(x4 + (size_t)es[i] * 32 + lane);
        acc_u4(acc, v0);
    }
    float inv = (e > b) ? 1.f / (float)(e - b) : 0.f;
    uint4 o;
    o.x = pack2h(acc[0] * inv, acc[1] * inv);
    o.y = pack2h(acc[2] * inv, acc[3] * inv);
    o.z = pack2h(acc[4] * inv, acc[5] * inv);
    o.w = pack2h(acc[6] * inv, acc[7] * inv);
    *reinterpret_cast<uint4*>(smem_agg + (lane >> 2) * 10240 + rl * 80 +
                              (lane & 3) * 16) = o;
}

// ======================= FUSED agg0 + layer-0+1 GEMM =================================
// Block = 128 rows. Phase A: aggregate into smem chunks 0-7 (K 0..255).
// Phase B: 2 N-passes of 128 cols; A chunks 8-15 (xc rows) + B staged via cp.async.
#define F1_AGG  0
#define F1_AX   81920
#define F1_BS   102400
#define F1_SMEM 122880

__global__ __launch_bounds__(256) void aggGemm1_kernel(int M) {
    extern __shared__ char smem[];
    const uint32_t smem_u = smem_to_u32(smem);
    int tid = threadIdx.x;
    int lane = tid & 31, wid = tid >> 5;
    int rb = blockIdx.x * 128;

    // ---- Phase A: aggregation (warp w handles local rows w*16 .. w*16+15) ----
    for (int rl = wid * 16; rl < wid * 16 + 16; rl++) {
        int d = rb + rl;
        if (d >= M) d = M - 1;
        agg_row_smem(g_off0, g_es0, g_xc, smem + F1_AGG, d, rl);
    }
    __syncthreads();

    // ---- Phase B: GEMM ----
    int warp_m = wid & 3, warp_n = wid >> 2;
    int hrow = tid >> 1;
    int hko = (tid & 1) * 32;
    int gr = rb + hrow;
    if (gr >= M) gr = M - 1;
    uint32_t aoff = (uint32_t)((warp_m * 32 + (lane & 15)) * 80 + ((lane >> 4) * 16));
    uint32_t boff = (uint32_t)((warp_n * 64 + (lane & 7) + ((lane >> 4) << 3)) * 80 +
                               (((lane >> 3) & 1) * 16));
    int gid = lane >> 2, tig = lane & 3;

    for (int np = 0; np < 2; np++) {
        __syncthreads();  // guard smem buffers across passes
        float acc[2][8][4] = {};

        auto cpAx = [&](int s, int par) {
            const char* src = reinterpret_cast<const char*>(g_xc) +
                              (size_t)gr * 512 + (s - 8) * 64 + hko;
            uint32_t dst = smem_u + F1_AX + par * 10240 + hrow * 80 + hko;
            CP_ASYNC16(dst, src);
            CP_ASYNC16(dst + 16, src + 16);
        };
        auto cpB = [&](int s, int par) {
            const char* src = reinterpret_cast<const char*>(g_Bh) +
                              (size_t)(np * 128 + hrow) * 1024 + (size_t)s * 64 + hko;
            uint32_t dst = smem_u + F1_BS + par * 10240 + hrow * 80 + hko;
            CP_ASYNC16(dst, src);
            CP_ASYNC16(dst + 16, src + 16);
        };

        cpB(0, 0);
        CP_COMMIT();

        for (int s = 0; s < 16; s++) {
            int par = s & 1;
            if (s < 15) {
                if (s + 1 >= 8) cpAx(s + 1, 1 - par);
                cpB(s + 1, 1 - par);
                CP_COMMIT();
                CP_WAIT(1);
            } else {
                CP_WAIT(0);
            }
            __syncthreads();

            uint32_t abase = (s < 8) ? (smem_u + F1_AGG + s * 10240)
                                     : (smem_u + F1_AX + par * 10240);
            uint32_t bbase = smem_u + F1_BS + par * 10240;
            #pragma unroll
            for (int k16 = 0; k16 < 2; k16++) {
                uint32_t ah[8];
                LDSM4(ah,     abase + aoff + k16 * 32);
                LDSM4(ah + 4, abase + aoff + 16 * 80 + k16 * 32);
                uint32_t bh[16];
                #pragma unroll
                for (int nt2 = 0; nt2 < 4; nt2++)
                    LDSM4(bh + nt2 * 4, bbase + boff + nt2 * 1280 + k16 * 32);
                #pragma unroll
                for (int mt = 0; mt < 2; mt++) {
                    #pragma unroll
                    for (int nt = 0; nt < 8; nt++)
                        MMA16816H(acc[mt][nt], ah + mt * 4, bh + nt * 2);
                }
            }
            __syncthreads();
        }

        // epilogue for this N-pass
        #pragma unroll
        for (int nt = 0; nt < 8; nt++) {
            int col = np * 128 + warp_n * 64 + nt * 8 + tig * 2;
            float bb0 = g_bB[col], bb1 = g_bB[col + 1];
            float ba0 = g_bA[col], ba1 = g_bA[col + 1];
            #pragma unroll
            for (int mt = 0; mt < 2; mt++) {
                #pragma unroll
                for (int hh = 0; hh < 2; hh++) {
                    int row = rb + warp_m * 32 + mt * 16 + gid + hh * 8;
                    if (row < M) {
                        bool c = g_cnt0[row] > 0;
                        float f0 = fmaxf(acc[mt][nt][hh * 2 + 0] + bb0 + (c ? ba0 : 0.f), 0.f);
                        float f1 = fmaxf(acc[mt][nt][hh * 2 + 1] + bb1 + (c ? ba1 : 0.f), 0.f);
                        *reinterpret_cast<uint32_t*>(&g_X1h[(size_t)row * HIDF + col]) =
                            pack2h(f0, f1);
                    }
                }
            }
        }
    }
}

// ======================= FUSED agg1 + layer-2 GEMM + log_softmax =====================
#define F2_AGG  0
#define F2_AX   81920
#define F2_SMEM 102400

__global__ __launch_bounds__(256) void aggGemm2_kernel(const float* __restrict__ b2,
                                                       float* __restrict__ out, int M) {
    extern __shared__ char smem[];
    const uint32_t smem_u = smem_to_u32(smem);
    int tid = threadIdx.x;
    int lane = tid & 31, wid = tid >> 5;
    int rb = blockIdx.x * 128;

    // ---- Phase A: aggregate Ag1 rows into smem chunks 0-7 ----
    for (int rl = wid * 16; rl < wid * 16 + 16; rl++) {
        int d = rb + rl;
        if (d >= M) d = M - 1;
        agg_row_smem(g_off1, g_es1, g_X1h, smem + F2_AGG, d, rl);
    }
    __syncthreads();

    // ---- Phase B: GEMM (N=64, B from fragment-ordered global) ----
    int hrow = tid >> 1;
    int hko = (tid & 1) * 32;
    int gr = rb + hrow;
    if (gr >= M) gr = M - 1;
    uint32_t aoff = (uint32_t)((wid * 16 + (lane & 15)) * 80 + ((lane >> 4) * 16));

    float acc[8][4] = {};

    auto cpAx = [&](int s, int par) {
        const char* src = reinterpret_cast<const char*>(g_X1h) +
                          (size_t)gr * 512 + (s - 8) * 64 + hko;
        uint32_t dst = smem_u + F2_AX + par * 10240 + hrow * 80 + hko;
        CP_ASYNC16(dst, src);
        CP_ASYNC16(dst + 16, src + 16);
    };

    for (int s = 0; s < 16; s++) {
        int par = s & 1;
        if (s >= 7 && s < 15) {
            cpAx(s + 1, 1 - par);
            CP_COMMIT();
            CP_WAIT(1);
        } else if (s == 15) {
            CP_WAIT(0);
        }
        __syncthreads();

        uint32_t abase = (s < 8) ? (smem_u + F2_AGG + s * 10240)
                                 : (smem_u + F2_AX + par * 10240);
        #pragma unroll
        for (int kk = 0; kk < 2; kk++) {
            int k16 = s * 2 + kk;
            uint32_t ah[4];
            LDSM4(ah, abase + aoff + kk * 32);
            #pragma unroll
            for (int nt = 0; nt < 8; nt++) {
                uint2 bh = __ldg(reinterpret_cast<const uint2*>(
                    g_W2f + ((size_t)(k16 * 8 + nt) * 32 + lane) * 2));
                MMA16816H(acc[nt], ah, reinterpret_cast<uint32_t*>(&bh));
            }
        }
        __syncthreads();
    }

    int gid = lane >> 2, tig = lane & 3;
    #pragma unroll
    for (int hh = 0; hh < 2; hh++) {
        int row = rb + wid * 16 + gid + hh * 8;
        float v[16];
        float m = -1e30f;
        #pragma unroll
        for (int nt = 0; nt < 8; nt++) {
            int col = nt * 8 + tig * 2;
            v[nt * 2 + 0] = acc[nt][hh * 2 + 0] + b2[col];
            v[nt * 2 + 1] = acc[nt][hh * 2 + 1] + b2[col + 1];
            m = fmaxf(m, fmaxf(v[nt * 2], v[nt * 2 + 1]));
        }
        m = fmaxf(m, __shfl_xor_sync(0xffffffffu, m, 1));
        m = fmaxf(m, __shfl_xor_sync(0xffffffffu, m, 2));
        float se = 0.f;
        #pragma unroll
        for (int i = 0; i < 16; i++) se += expf(v[i] - m);
        se += __shfl_xor_sync(0xffffffffu, se, 1);
        se += __shfl_xor_sync(0xffffffffu, se, 2);
        float lse = m + logf(se);
        if (row < M) {
            #pragma unroll
            for (int nt = 0; nt < 8; nt++) {
                float2 r;
                r.x = v[nt * 2 + 0] - lse;
                r.y = v[nt * 2 + 1] - lse;
                *reinterpret_cast<float2*>(&out[(size_t)row * OUTF + nt * 8 + tig * 2]) = r;
            }
        }
    }
}

// ======================= launch =======================
extern "C" void kernel_launch(void* const* d_in, const int* in_sizes, int n_in,
                              void* d_out, int out_size) {
    const float* x_tar   = (const float*)d_in[0];
    const float* x_neigh = (const float*)d_in[1];
    const int* esrc0 = (const int*)d_in[2];
    const int* edst0 = (const int*)d_in[3];
    const int* esrc1 = (const int*)d_in[4];
    const int* edst1 = (const int*)d_in[5];
    const float* Wl0 = (const float*)d_in[8];
    const float* Wr0 = (const float*)d_in[9];
    const float* b0  = (const float*)d_in[10];
    const float* Wl1 = (const float*)d_in[11];
    const float* Wr1 = (const float*)d_in[12];
    const float* b1  = (const float*)d_in[13];
    const float* Wl2 = (const float*)d_in[14];
    const float* Wr2 = (const float*)d_in[15];
    const float* b2  = (const float*)d_in[16];
    int E0 = in_sizes[2];
    int E1 = in_sizes[4];
    int M1 = N1C;
    int M2 = out_size / OUTF;
    float* out = (float*)d_out;

    cudaFuncSetAttribute(aggGemm1_kernel,
                         cudaFuncAttributeMaxDynamicSharedMemorySize, F1_SMEM);
    cudaFuncSetAttribute(aggGemm2_kernel,
                         cudaFuncAttributeMaxDynamicSharedMemorySize, F2_SMEM);

    zero_cvt_kernel<<<ZB + CVB, 256>>>(x_neigh, x_tar);

    int EALL = E0 + E1;
    int ncb = (EALL + 255) / 256;
    countprep_kernel<<<ncb + WCB + W2B + 1, 256>>>(
        edst0, edst1, E0, E1, ncb, Wl0, Wr0, b0, Wl1, Wr1, b1, Wl2, Wr2);
    scanPart_all<<<NB0 + NB1, 256>>>();
    scanTop_all<<<1, 256>>>();
    scanFinal_all<<<NB0 + NB1, 256>>>();
    scatterAll_kernel<<<(EALL + 255) / 256, 256>>>(esrc0, edst0, esrc1, edst1, E0, E1);

    aggGemm1_kernel<<<(M1 + 127) / 128, 256, F1_SMEM>>>(M1);
    aggGemm2_kernel<<<(M2 + 127) / 128, 256, F2_SMEM>>>(b2, out, M2);
}

// round 17
// speedup vs baseline: 1.5025x; 1.5025x over previous
#include <cuda_runtime.h>
#include <cuda_fp16.h>
#include <cstdint>

#define INF   128
#define HIDF  256
#define OUTF  64
#define N0C   400000
#define N1C   100000
#define N2C   25000
#define E0C   1600000
#define E1C   400000

// ======================= PTX helpers =======================
__device__ __forceinline__ uint32_t smem_to_u32(const void* smem_ptr) {
    uint32_t addr;
    asm("{ .reg .u64 tmp; cvta.to.shared.u64 tmp, %1; cvt.u32.u64 %0, tmp; }"
        : "=r"(addr) : "l"(smem_ptr));
    return addr;
}
#define CP_ASYNC16(dst, src) \
    asm volatile("cp.async.cg.shared.global [%0], [%1], 16;" :: "r"(dst), "l"(src))
#define CP_COMMIT() asm volatile("cp.async.commit_group;" ::: "memory")
#define CP_WAIT(n)  asm volatile("cp.async.wait_group %0;" :: "n"(n) : "memory")
#define LDSM4(r, addr) \
    asm volatile("ldmatrix.sync.aligned.m8n8.x4.shared.b16 {%0,%1,%2,%3}, [%4];" \
        : "=r"((r)[0]), "=r"((r)[1]), "=r"((r)[2]), "=r"((r)[3]) : "r"(addr))
#define MMA16816H(d, a, b) \
    asm volatile("mma.sync.aligned.m16n8k16.row.col.f32.f16.f16.f32 " \
        "{%0,%1,%2,%3}, {%4,%5,%6,%7}, {%8,%9}, {%0,%1,%2,%3};" \
        : "+f"((d)[0]), "+f"((d)[1]), "+f"((d)[2]), "+f"((d)[3]) \
        : "r"((a)[0]), "r"((a)[1]), "r"((a)[2]), "r"((a)[3]), \
          "r"((b)[0]), "r"((b)[1]))

__device__ __forceinline__ uint32_t pack2h(float a, float b) {
    __half2 p = __floats2half2_rn(a, b);
    return *reinterpret_cast<uint32_t*>(&p);
}

// ======================= device scratch =======================
__device__ __align__(16) __half g_xc[(size_t)N0C * 256];    // [row][xn(128)|xt(128)] fp16
__device__ __align__(16) __half g_Ac[(size_t)N1C * 256];    // [row][An(128)|At(128)] fp16
__device__ __align__(16) __half g_X1h[(size_t)N1C * HIDF];  // layer-1 output fp16
__device__ __align__(16) __half g_Ag1h[(size_t)N2C * HIDF]; // level-1 aggregate fp16
__device__ int g_cnt0[N1C];
__device__ int g_off0[N1C + 1];
__device__ int g_cur0[N1C];
__device__ int g_es0[E0C];
__device__ int g_cnt1[N2C];
__device__ int g_off1[N2C + 1];
__device__ int g_cur1[N2C];
__device__ int g_es1[E1C];
__device__ int g_part0[256];
__device__ int g_part1[64];
__device__ __align__(128) __half g_Bh[256 * 512];           // [N=256][K=512] combined W fp16
__device__ __align__(16) uint32_t g_W2f[64 * 512 / 2];      // W2 fp16, mma fragment order
__device__ float g_bA[HIDF];
__device__ float g_bB[HIDF];

// ======================= fused zero + weight prep + x->fp16 convert ===================
#define ZB  489
#define WCB 512
#define W2B 128
#define CVB ((N0C * 256) / 2048)   // 50000 convert blocks (8 rows per block)
__global__ void zero_prep_kernel(
    const float* __restrict__ xn, const float* __restrict__ xt,
    const float* __restrict__ Wl0, const float* __restrict__ Wr0,
    const float* __restrict__ b0,
    const float* __restrict__ Wl1, const float* __restrict__ Wr1,
    const float* __restrict__ b1,
    const float* __restrict__ Wl2, const float* __restrict__ Wr2) {
    int b = blockIdx.x, t = threadIdx.x;
    if (b < ZB) {
        int i = b * 256 + t;
        if (i < N1C) g_cnt0[i] = 0;
        else if (i < N1C + N2C) g_cnt1[i - N1C] = 0;
    } else if (b < ZB + WCB) {
        int idx = (b - ZB) * 256 + t;
        int i = idx >> 8;                  // K 0..511
        int j = idx & 255;                 // N 0..255
        int blk = i >> 7;
        int il = i & 127;
        const float* M1 = (blk == 0 || blk == 2) ? Wl0 : Wr0;
        const float* M2 = (blk < 2) ? Wl1 : Wr1;
        float s = 0.f;
        #pragma unroll 8
        for (int k = 0; k < 256; k++) s = fmaf(M1[il * 256 + k], M2[k * 256 + j], s);
        g_Bh[j * 512 + i] = __float2half_rn(s);
    } else if (b < ZB + WCB + W2B) {
        int e = (b - ZB - WCB) * 256 + t;
        int n = e & 63, k = e >> 6;
        float s = (k < 256) ? Wl2[k * 64 + n] : Wr2[(k - 256) * 64 + n];
        int k16 = k >> 4, nt = n >> 3, gid = n & 7;
        int kk = k & 15, reg = kk >> 3, tig = (kk & 7) >> 1, half = kk & 1;
        int u = ((k16 * 8 + nt) * 32 + gid * 4 + tig) * 2 + reg;
        reinterpret_cast<__half*>(g_W2f)[u * 2 + half] = __float2half_rn(s);
    } else if (b == ZB + WCB + W2B) {
        int j = t;
        float sa = 0.f, sb = 0.f;
        for (int k = 0; k < 256; k++) {
            sa = fmaf(b0[k], Wl1[k * 256 + j], sa);
            sb = fmaf(b0[k], Wr1[k * 256 + j], sb);
        }
        g_bA[j] = sa;
        g_bB[j] = sb + b1[j];
    } else {
        // convert x -> g_xc fp16 interleaved: row = [xn(128) | xt(128)]
        int cb = b - (ZB + WCB + W2B + 1);
        int idx = cb * 2048 + t * 8;
        int row = idx >> 8;
        int pos = idx & 255;
        const float* src = (pos < 128) ? (xn + (size_t)row * 128 + pos)
                                       : (xt + (size_t)row * 128 + (pos - 128));
        float4 a = __ldg(reinterpret_cast<const float4*>(src));
        float4 c = __ldg(reinterpret_cast<const float4*>(src) + 1);
        uint4 o;
        o.x = pack2h(a.x, a.y);
        o.y = pack2h(a.z, a.w);
        o.z = pack2h(c.x, c.y);
        o.w = pack2h(c.z, c.w);
        *reinterpret_cast<uint4*>(g_xc + (size_t)row * 256 + pos) = o;
    }
}

// ======================= merged bookkeeping =======================
__global__ void countAll_kernel(const int* __restrict__ d0, const int* __restrict__ d1,
                                int e0, int e1) {
    int i = blockIdx.x * blockDim.x + threadIdx.x;
    if (i < e0) atomicAdd(&g_cnt0[d0[i]], 1);
    else if (i - e0 < e1) atomicAdd(&g_cnt1[d1[i - e0]], 1);
}
__global__ void scatterAll_kernel(const int* __restrict__ s0, const int* __restrict__ d0,
                                  const int* __restrict__ s1, const int* __restrict__ d1,
                                  int e0, int e1) {
    int i = blockIdx.x * blockDim.x + threadIdx.x;
    if (i < e0) {
        int p = atomicAdd(&g_cur0[d0[i]], 1);
        g_es0[p] = s0[i];
    } else if (i - e0 < e1) {
        int j = i - e0;
        int p = atomicAdd(&g_cur1[d1[j]], 1);
        g_es1[p] = s1[j];
    }
}

#define NB0 ((N1C + 511) / 512)
#define NB1 ((N2C + 511) / 512)

__device__ __forceinline__ void scan_part_impl(const int* __restrict__ cnt,
                                               int* __restrict__ part, int n, int bb) {
    __shared__ int ws[8];
    int base = bb * 512;
    int t = threadIdx.x;
    int i0 = base + t * 2;
    int s = 0;
    if (i0 < n) s += cnt[i0];
    if (i0 + 1 < n) s += cnt[i0 + 1];
    #pragma unroll
    for (int o = 16; o > 0; o >>= 1) s += __shfl_down_sync(0xffffffffu, s, o);
    if ((t & 31) == 0) ws[t >> 5] = s;
    __syncthreads();
    if (t == 0) {
        int tot = 0;
        #pragma unroll
        for (int i = 0; i < 8; i++) tot += ws[i];
        part[bb] = tot;
    }
}
__device__ __forceinline__ void scan_top_impl(int* __restrict__ part, int nb) {
    __shared__ int ws[8];
    int t = threadIdx.x;
    int v = (t < nb) ? part[t] : 0;
    int lane = t & 31, w = t >> 5;
    int incl = v;
    #pragma unroll
    for (int o = 1; o < 32; o <<= 1) {
        int x = __shfl_up_sync(0xffffffffu, incl, o);
        if (lane >= o) incl += x;
    }
    if (lane == 31) ws[w] = incl;
    __syncthreads();
    if (t == 0) {
        int run = 0;
        #pragma unroll
        for (int i = 0; i < 8; i++) { int tm = ws[i]; ws[i] = run; run += tm; }
    }
    __syncthreads();
    if (t < nb) part[t] = incl - v + ws[w];
    __syncthreads();
}
__device__ __forceinline__ void scan_final_impl(const int* __restrict__ cnt,
                                                const int* __restrict__ part,
                                                int* __restrict__ off,
                                                int* __restrict__ cur, int n, int bb) {
    __shared__ int ws[8];
    int base = bb * 512;
    int t = threadIdx.x;
    int i0 = base + t * 2;
    int c0 = (i0 < n) ? cnt[i0] : 0;
    int c1 = (i0 + 1 < n) ? cnt[i0 + 1] : 0;
    int s = c0 + c1;
    int lane = t & 31, w = t >> 5;
    int incl = s;
    #pragma unroll
    for (int o = 1; o < 32; o <<= 1) {
        int x = __shfl_up_sync(0xffffffffu, incl, o);
        if (lane >= o) incl += x;
    }
    if (lane == 31) ws[w] = incl;
    __syncthreads();
    if (t == 0) {
        int run = 0;
        #pragma unroll
        for (int i = 0; i < 8; i++) { int tm = ws[i]; ws[i] = run; run += tm; }
    }
    __syncthreads();
    int excl = incl - s + ws[w] + part[bb];
    if (i0 < n) { off[i0] = excl; cur[i0] = excl; }
    if (i0 + 1 < n) { off[i0 + 1] = excl + c0; cur[i0 + 1] = excl + c0; }
    if (i0 == n - 1) off[n] = excl + c0;
    else if (i0 + 1 == n - 1) off[n] = excl + c0 + c1;
}
__global__ void scanPart_all() {
    int b = blockIdx.x;
    if (b < NB0) scan_part_impl(g_cnt0, g_part0, N1C, b);
    else scan_part_impl(g_cnt1, g_part1, N2C, b - NB0);
}
__global__ void scanTop_all() {
    scan_top_impl(g_part0, NB0);
    scan_top_impl(g_part1, NB1);
}
__global__ void scanFinal_all() {
    int b = blockIdx.x;
    if (b < NB0) scan_final_impl(g_cnt0, g_part0, g_off0, g_cur0, N1C, b);
    else scan_final_impl(g_cnt1, g_part1, g_off1, g_cur1, N2C, b - NB0);
}

// ======================= aggregation (fp16 gather, fp32 accumulate) ===================
__device__ __forceinline__ void acc_u4(float* acc, uint4 v) {
    const __half2* h = reinterpret_cast<const __half2*>(&v);
    #pragma unroll
    for (int q = 0; q < 4; q++) {
        float2 f = __half22float2(h[q]);
        acc[q * 2 + 0] += f.x;
        acc[q * 2 + 1] += f.y;
    }
}

// one warp per dst node: gathers 512B fp16 rows (R8-proven 2-edge unroll)
__global__ __launch_bounds__(256) void agg0_kernel() {
    int w = threadIdx.x >> 5, lane = threadIdx.x & 31;
    int d = blockIdx.x * 8 + w;
    if (d >= N1C) return;
    int b = g_off0[d], e = g_off0[d + 1];
    const uint4* xc4 = reinterpret_cast<const uint4*>(g_xc);
    float acc[8] = {};
    int i = b;
    for (; i + 1 < e; i += 2) {
        int s0 = g_es0[i], s1 = g_es0[i + 1];
        uint4 v0 = __ldg(xc4 + (size_t)s0 * 32 + lane);
        uint4 v1 = __ldg(xc4 + (size_t)s1 * 32 + lane);
        acc_u4(acc, v0);
        acc_u4(acc, v1);
    }
    if (i < e) {
        uint4 v0 = __ldg(xc4 + (size_t)g_es0[i] * 32 + lane);
        acc_u4(acc, v0);
    }
    float inv = (e > b) ? 1.f / (float)(e - b) : 0.f;
    uint4 o;
    o.x = pack2h(acc[0] * inv, acc[1] * inv);
    o.y = pack2h(acc[2] * inv, acc[3] * inv);
    o.z = pack2h(acc[4] * inv, acc[5] * inv);
    o.w = pack2h(acc[6] * inv, acc[7] * inv);
    reinterpret_cast<uint4*>(g_Ac)[(size_t)d * 32 + lane] = o;
}

__global__ __launch_bounds__(256) void agg1_kernel() {
    int w = threadIdx.x >> 5, lane = threadIdx.x & 31;
    int d = blockIdx.x * 8 + w;
    if (d >= N2C) return;
    int b = g_off1[d], e = g_off1[d + 1];
    const uint4* x4 = reinterpret_cast<const uint4*>(g_X1h);
    float acc[8] = {};
    int i = b;
    for (; i + 1 < e; i += 2) {
        int s0 = g_es1[i], s1 = g_es1[i + 1];
        uint4 v0 = __ldg(x4 + (size_t)s0 * 32 + lane);
        uint4 v1 = __ldg(x4 + (size_t)s1 * 32 + lane);
        acc_u4(acc, v0);
        acc_u4(acc, v1);
    }
    if (i < e) {
        uint4 v0 = __ldg(x4 + (size_t)g_es1[i] * 32 + lane);
        acc_u4(acc, v0);
    }
    float inv = (e > b) ? 1.f / (float)(e - b) : 0.f;
    uint4 o;
    o.x = pack2h(acc[0] * inv, acc[1] * inv);
    o.y = pack2h(acc[2] * inv, acc[3] * inv);
    o.z = pack2h(acc[4] * inv, acc[5] * inv);
    o.w = pack2h(acc[6] * inv, acc[7] * inv);
    reinterpret_cast<uint4*>(g_Ag1h)[(size_t)d * 32 + lane] = o;
}

// ======================= HMMA fused layer-0+1 GEMM (3-stage cp.async) =================
#define G1_A     0
#define G1_B     10240
#define G1_STAGE 20480
#define GEMM1_SMEM (3 * G1_STAGE)

__global__ __launch_bounds__(256) void gemm1_mma_kernel(int M) {
    extern __shared__ char smem[];
    const uint32_t smem_u = smem_to_u32(smem);
    int tid = threadIdx.x;
    int lane = tid & 31, wid = tid >> 5;
    int warp_m = wid & 3, warp_n = wid >> 2;
    int rowbase = blockIdx.y * 128;
    int colbase = blockIdx.x * 128;

    int hrow = tid >> 1;
    int hko = (tid & 1) * 32;

    uint32_t aoff = (uint32_t)((warp_m * 32 + (lane & 15)) * 80 + ((lane >> 4) * 16));
    uint32_t boff = (uint32_t)((warp_n * 64 + (lane & 7) + ((lane >> 4) << 3)) * 80 +
                               (((lane >> 3) & 1) * 16));

    float acc[2][8][4] = {};

    int gr = rowbase + hrow;
    if (gr >= M) gr = M - 1;

    auto cpStage = [&](int s) {
        int par = s % 3;
        const char* srcA = (s < 8)
            ? reinterpret_cast<const char*>(g_Ac + (size_t)gr * 256 + s * 32)
            : reinterpret_cast<const char*>(g_xc + (size_t)gr * 256 + (s - 8) * 32);
        srcA += hko;
        uint32_t dstA = smem_u + par * G1_STAGE + G1_A + hrow * 80 + hko;
        CP_ASYNC16(dstA, srcA);
        CP_ASYNC16(dstA + 16, srcA + 16);
        const char* srcB = reinterpret_cast<const char*>(g_Bh) +
                           (size_t)(colbase + hrow) * 1024 + (size_t)s * 64 + hko;
        uint32_t dstB = smem_u + par * G1_STAGE + G1_B + hrow * 80 + hko;
        CP_ASYNC16(dstB, srcB);
        CP_ASYNC16(dstB + 16, srcB + 16);
        CP_COMMIT();
    };

    cpStage(0);
    cpStage(1);

    for (int s = 0; s < 16; s++) {
        if (s + 2 < 16) {
            cpStage(s + 2);
            CP_WAIT(2);
        } else if (s + 1 < 16) {
            CP_WAIT(1);
        } else {
            CP_WAIT(0);
        }
        __syncthreads();

        uint32_t sb = smem_u + (s % 3) * G1_STAGE;
        #pragma unroll
        for (int k16 = 0; k16 < 2; k16++) {
            uint32_t ah[8];
            LDSM4(ah,     sb + G1_A + aoff + k16 * 32);
            LDSM4(ah + 4, sb + G1_A + aoff + 16 * 80 + k16 * 32);
            uint32_t bh[16];
            #pragma unroll
            for (int nt2 = 0; nt2 < 4; nt2++)
                LDSM4(bh + nt2 * 4, sb + G1_B + boff + nt2 * 1280 + k16 * 32);
            #pragma unroll
            for (int mt = 0; mt < 2; mt++) {
                #pragma unroll
                for (int nt = 0; nt < 8; nt++)
                    MMA16816H(acc[mt][nt], ah + mt * 4, bh + nt * 2);
            }
        }
        __syncthreads();
    }

    int gid = lane >> 2, tig = lane & 3;
    #pragma unroll
    for (int nt = 0; nt < 8; nt++) {
        int col = colbase + warp_n * 64 + nt * 8 + tig * 2;
        float bb0 = g_bB[col], bb1 = g_bB[col + 1];
        float ba0 = g_bA[col], ba1 = g_bA[col + 1];
        #pragma unroll
        for (int mt = 0; mt < 2; mt++) {
            #pragma unroll
            for (int hh = 0; hh < 2; hh++) {
                int row = rowbase + warp_m * 32 + mt * 16 + gid + hh * 8;
                if (row < M) {
                    bool c = g_cnt0[row] > 0;
                    float f0 = fmaxf(acc[mt][nt][hh * 2 + 0] + bb0 + (c ? ba0 : 0.f), 0.f);
                    float f1 = fmaxf(acc[mt][nt][hh * 2 + 1] + bb1 + (c ? ba1 : 0.f), 0.f);
                    *reinterpret_cast<uint32_t*>(&g_X1h[(size_t)row * HIDF + col]) =
                        pack2h(f0, f1);
                }
            }
        }
    }
}

// ======================= layer-2 HMMA GEMM + fused log_softmax =======================
#define G2_STAGE 10240
__global__ __launch_bounds__(256) void gemm2_mma_kernel(const float* __restrict__ b2,
                                                        float* __restrict__ out, int M) {
    __shared__ __align__(16) char smem[2 * G2_STAGE];
    const uint32_t smem_u = smem_to_u32(smem);
    int tid = threadIdx.x;
    int lane = tid & 31, wid = tid >> 5;
    int rowbase = blockIdx.x * 128;

    int hrow = tid >> 1;
    int hko = (tid & 1) * 32;
    uint32_t aoff = (uint32_t)((wid * 16 + (lane & 15)) * 80 + ((lane >> 4) * 16));

    float acc[8][4] = {};

    int gr = rowbase + hrow;
    if (gr >= M) gr = M - 1;

    auto cpA = [&](int s, int par) {
        const char* src = (s < 8)
            ? reinterpret_cast<const char*>(g_Ag1h + (size_t)gr * 256 + s * 32)
            : reinterpret_cast<const char*>(g_X1h + (size_t)gr * 256 + (s - 8) * 32);
        src += hko;
        uint32_t dst = smem_u + par * G2_STAGE + hrow * 80 + hko;
        CP_ASYNC16(dst, src);
        CP_ASYNC16(dst + 16, src + 16);
    };

    cpA(0, 0);
    CP_COMMIT();
    for (int s = 0; s < 16; s++) {
        int par = s & 1;
        if (s < 15) {
            cpA(s + 1, 1 - par);
            CP_COMMIT();
            CP_WAIT(1);
        } else {
            CP_WAIT(0);
        }
        __syncthreads();
        uint32_t sb = smem_u + par * G2_STAGE;
        #pragma unroll
        for (int kk = 0; kk < 2; kk++) {
            int k16 = s * 2 + kk;
            uint32_t ah[4];
            LDSM4(ah, sb + aoff + kk * 32);
            #pragma unroll
            for (int nt = 0; nt < 8; nt++) {
                uint2 bh = __ldg(reinterpret_cast<const uint2*>(
                    g_W2f + ((size_t)(k16 * 8 + nt) * 32 + lane) * 2));
                MMA16816H(acc[nt], ah, reinterpret_cast<uint32_t*>(&bh));
            }
        }
        __syncthreads();
    }

    int gid = lane >> 2, tig = lane & 3;
    #pragma unroll
    for (int hh = 0; hh < 2; hh++) {
        int row = rowbase + wid * 16 + gid + hh * 8;
        float v[16];
        float m = -1e30f;
        #pragma unroll
        for (int nt = 0; nt < 8; nt++) {
            int col = nt * 8 + tig * 2;
            v[nt * 2 + 0] = acc[nt][hh * 2 + 0] + b2[col];
            v[nt * 2 + 1] = acc[nt][hh * 2 + 1] + b2[col + 1];
            m = fmaxf(m, fmaxf(v[nt * 2], v[nt * 2 + 1]));
        }
        m = fmaxf(m, __shfl_xor_sync(0xffffffffu, m, 1));
        m = fmaxf(m, __shfl_xor_sync(0xffffffffu, m, 2));
        float se = 0.f;
        #pragma unroll
        for (int i = 0; i < 16; i++) se += expf(v[i] - m);
        se += __shfl_xor_sync(0xffffffffu, se, 1);
        se += __shfl_xor_sync(0xffffffffu, se, 2);
        float lse = m + logf(se);
        if (row < M) {
            #pragma unroll
            for (int nt = 0; nt < 8; nt++) {
                float2 r;
                r.x = v[nt * 2 + 0] - lse;
                r.y = v[nt * 2 + 1] - lse;
                *reinterpret_cast<float2*>(&out[(size_t)row * OUTF + nt * 8 + tig * 2]) = r;
            }
        }
    }
}

// ======================= launch =======================
extern "C" void kernel_launch(void* const* d_in, const int* in_sizes, int n_in,
                              void* d_out, int out_size) {
    const float* x_tar   = (const float*)d_in[0];
    const float* x_neigh = (const float*)d_in[1];
    const int* esrc0 = (const int*)d_in[2];
    const int* edst0 = (const int*)d_in[3];
    const int* esrc1 = (const int*)d_in[4];
    const int* edst1 = (const int*)d_in[5];
    const float* Wl0 = (const float*)d_in[8];
    const float* Wr0 = (const float*)d_in[9];
    const float* b0  = (const float*)d_in[10];
    const float* Wl1 = (const float*)d_in[11];
    const float* Wr1 = (const float*)d_in[12];
    const float* b1  = (const float*)d_in[13];
    const float* Wl2 = (const float*)d_in[14];
    const float* Wr2 = (const float*)d_in[15];
    const float* b2  = (const float*)d_in[16];
    int E0 = in_sizes[2];
    int E1 = in_sizes[4];
    int M1 = N1C;
    int M2 = out_size / OUTF;
    float* out = (float*)d_out;

    cudaFuncSetAttribute(gemm1_mma_kernel,
                         cudaFuncAttributeMaxDynamicSharedMemorySize, GEMM1_SMEM);

    zero_prep_kernel<<<ZB + WCB + W2B + 1 + CVB, 256>>>(
        x_neigh, x_tar, Wl0, Wr0, b0, Wl1, Wr1, b1, Wl2, Wr2);

    int EALL = E0 + E1;
    countAll_kernel<<<(EALL + 255) / 256, 256>>>(edst0, edst1, E0, E1);
    scanPart_all<<<NB0 + NB1, 256>>>();
    scanTop_all<<<1, 256>>>();
    scanFinal_all<<<NB0 + NB1, 256>>>();
    scatterAll_kernel<<<(EALL + 255) / 256, 256>>>(esrc0, edst0, esrc1, edst1, E0, E1);
    agg0_kernel<<<(N1C + 7) / 8, 256>>>();

    dim3 g1(2, (M1 + 127) / 128);
    gemm1_mma_kernel<<<g1, 256, GEMM1_SMEM>>>(M1);

    agg1_kernel<<<(N2C + 7) / 8, 256>>>();
    gemm2_mma_kernel<<<(M2 + 127) / 128, 256>>>(b2, out, M2);
}